// round 1
// baseline (speedup 1.0000x reference)
#include <cuda_runtime.h>
#include <cstdint>

// ---------------------------------------------------------------------------
// ShiftedWindowMSA  (B=32, 56x56, EMB=256, 8 heads, 7x7 windows)
//
// Stage 1: permute w1 columns once:  j_new = g*32 + e  <->  j_orig = e*24 + g
//          (g = head*3 + which, e = channel within head)
// Stage 2: QKV GEMM (tf32 mma.sync m16n8k8), epilogue scatters into
//          scratch[b][g][win][ws][e] applying roll(-4,-4) + window partition.
// Stage 3: per-window attention (49x32), bias + shift masks + softmax,
//          writes output applying inverse roll(+3,+3).
// ---------------------------------------------------------------------------

#define NB    32
#define HPIX  56
#define EMBD  256
#define NHEAD 8
#define WSZ   49
#define MROWS 100352            // 32*56*56
#define ROWSTRIDE 100352        // 64 windows * 49 * 32 per (b,g)

__device__ float g_scr[(size_t)NB * 24 * ROWSTRIDE];  // 308 MB scratch
__device__ float g_w1p[256 * 768];
__device__ float g_b1p[768];

__device__ __forceinline__ float to_tf32(float x) {
    uint32_t u;
    asm("cvt.rna.tf32.f32 %0, %1;" : "=r"(u) : "f"(x));
    return __uint_as_float(u);
}

// ---------------------------------------------------------------------------
// Stage 1: permute w1 / b1
// ---------------------------------------------------------------------------
__global__ void permute_w1_kernel(const float* __restrict__ w1,
                                  const float* __restrict__ b1) {
    int idx = blockIdx.x * blockDim.x + threadIdx.x;
    if (idx < 256 * 768) {
        int k = idx / 768, jn = idx - k * 768;
        int g = jn >> 5, e = jn & 31;
        g_w1p[idx] = w1[k * 768 + e * 24 + g];
    }
    if (idx < 768) {
        int g = idx >> 5, e = idx & 31;
        g_b1p[idx] = b1[e * 24 + g];
    }
}

// ---------------------------------------------------------------------------
// Stage 2: QKV GEMM  C[100352,768] = x[100352,256] @ w1p[256,768] + b1p
//   CTA tile 128x128, BK=32, 8 warps (2x4), warp tile 64x32, tf32 mma.
//   Epilogue scatters rows through roll(-4) + window partition.
// ---------------------------------------------------------------------------
#define BM 128
#define BN 128
#define BK 32
#define ASTR 36    // (row*36 + k) % 32 == (4*row + k) % 32 -> conflict free
#define BSTR 136   // (k*136 + n) % 32 == (8*k + n) % 32   -> conflict free

__global__ __launch_bounds__(256) void qkv_gemm_kernel(const float* __restrict__ x) {
    __shared__ float As[BM * ASTR];
    __shared__ float Bs[BK * BSTR];

    const int tid  = threadIdx.x;
    const int warp = tid >> 5, lane = tid & 31;
    const int tg = lane >> 2, t4 = lane & 3;
    const int wm0 = (warp >> 2) * 64;
    const int wn0 = (warp & 3) * 32;
    const int tile_m = blockIdx.x * BM;
    const int tile_n = blockIdx.y * BN;

    float c[4][4][4];
#pragma unroll
    for (int a = 0; a < 4; a++)
#pragma unroll
        for (int b = 0; b < 4; b++)
#pragma unroll
            for (int d = 0; d < 4; d++) c[a][b][d] = 0.f;

    for (int ki = 0; ki < 256; ki += BK) {
        // A tile: 128 x 32 (float4, tf32-rounded)
#pragma unroll
        for (int j = 0; j < 4; j++) {
            int f = tid + j * 256;
            int row = f >> 3, c4 = (f & 7) * 4;
            float4 va = *reinterpret_cast<const float4*>(
                x + (size_t)(tile_m + row) * 256 + ki + c4);
            float4 t;
            t.x = to_tf32(va.x); t.y = to_tf32(va.y);
            t.z = to_tf32(va.z); t.w = to_tf32(va.w);
            *reinterpret_cast<float4*>(&As[row * ASTR + c4]) = t;
        }
        // B tile: 32 x 128
#pragma unroll
        for (int j = 0; j < 4; j++) {
            int f = tid + j * 256;
            int kr = f >> 5, c4 = (f & 31) * 4;
            float4 vb = *reinterpret_cast<const float4*>(
                &g_w1p[(size_t)(ki + kr) * 768 + tile_n + c4]);
            float4 t;
            t.x = to_tf32(vb.x); t.y = to_tf32(vb.y);
            t.z = to_tf32(vb.z); t.w = to_tf32(vb.w);
            *reinterpret_cast<float4*>(&Bs[kr * BSTR + c4]) = t;
        }
        __syncthreads();

#pragma unroll
        for (int kk = 0; kk < 32; kk += 8) {
            uint32_t a[4][4], bf[4][2];
#pragma unroll
            for (int mt = 0; mt < 4; mt++) {
                int r = wm0 + mt * 16 + tg;
                a[mt][0] = __float_as_uint(As[r * ASTR + kk + t4]);
                a[mt][1] = __float_as_uint(As[(r + 8) * ASTR + kk + t4]);
                a[mt][2] = __float_as_uint(As[r * ASTR + kk + t4 + 4]);
                a[mt][3] = __float_as_uint(As[(r + 8) * ASTR + kk + t4 + 4]);
            }
#pragma unroll
            for (int nt = 0; nt < 4; nt++) {
                int cn = wn0 + nt * 8 + tg;
                bf[nt][0] = __float_as_uint(Bs[(kk + t4) * BSTR + cn]);
                bf[nt][1] = __float_as_uint(Bs[(kk + t4 + 4) * BSTR + cn]);
            }
#pragma unroll
            for (int mt = 0; mt < 4; mt++)
#pragma unroll
                for (int nt = 0; nt < 4; nt++)
                    asm volatile(
                        "mma.sync.aligned.m16n8k8.row.col.f32.tf32.tf32.f32 "
                        "{%0,%1,%2,%3}, {%4,%5,%6,%7}, {%8,%9}, {%0,%1,%2,%3};"
                        : "+f"(c[mt][nt][0]), "+f"(c[mt][nt][1]),
                          "+f"(c[mt][nt][2]), "+f"(c[mt][nt][3])
                        : "r"(a[mt][0]), "r"(a[mt][1]), "r"(a[mt][2]), "r"(a[mt][3]),
                          "r"(bf[nt][0]), "r"(bf[nt][1]));
        }
        __syncthreads();
    }

    // Epilogue: scatter through roll(-4) + window partition.
    size_t rowbase[8];
#pragma unroll
    for (int mt = 0; mt < 4; mt++) {
#pragma unroll
        for (int h = 0; h < 2; h++) {
            int n = tile_m + wm0 + mt * 16 + tg + h * 8;
            int b = n / 3136;
            int r = n - b * 3136;
            int y = r / 56, xx = r - y * 56;
            int yr = (y + 52) % 56;    // rolled coord (roll by -4)
            int xr = (xx + 52) % 56;
            int u = yr / 7, wxr = yr - u * 7;
            int v = xr / 7, wyr = xr - v * 7;
            rowbase[mt * 2 + h] = (size_t)(b * 24) * ROWSTRIDE
                                + (size_t)(u * 8 + v) * (WSZ * 32)
                                + (size_t)(wxr * 7 + wyr) * 32;
        }
    }
#pragma unroll
    for (int nt = 0; nt < 4; nt++) {
        int jn0 = tile_n + wn0 + nt * 8 + t4 * 2;
        float bias0 = g_b1p[jn0];
        float bias1 = g_b1p[jn0 + 1];
        int g0 = jn0 >> 5, e0 = jn0 & 31;   // jn0 even -> jn0+1 same g
        size_t coff = (size_t)g0 * ROWSTRIDE + e0;
#pragma unroll
        for (int mt = 0; mt < 4; mt++) {
            g_scr[rowbase[mt * 2 + 0] + coff]     = c[mt][nt][0] + bias0;
            g_scr[rowbase[mt * 2 + 0] + coff + 1] = c[mt][nt][1] + bias1;
            g_scr[rowbase[mt * 2 + 1] + coff]     = c[mt][nt][2] + bias0;
            g_scr[rowbase[mt * 2 + 1] + coff + 1] = c[mt][nt][3] + bias1;
        }
    }
}

// ---------------------------------------------------------------------------
// Stage 3: per-window attention. One 64-thread block per (b, head, window).
// ---------------------------------------------------------------------------
__global__ __launch_bounds__(64) void attn_kernel(const float* __restrict__ pos,
                                                  float* __restrict__ out) {
    __shared__ float sq[WSZ * 36];
    __shared__ float sk[WSZ * 36];
    __shared__ float sv[WSZ * 36];
    __shared__ float sS[WSZ * 50];
    __shared__ float sPos[169];

    const int tid = threadIdx.x;
    const int bid = blockIdx.x;
    const int b    = bid >> 9;
    const int head = (bid >> 6) & 7;
    const int win  = bid & 63;
    const int u = win >> 3, v = win & 7;

    const float* base = g_scr + (size_t)(b * 24 + head * 3) * ROWSTRIDE
                              + (size_t)win * (WSZ * 32);

    // load q,k,v: 3 * 49*32 floats = 1176 float4
    for (int t = tid; t < 1176; t += 64) {
        int which = t / 392;
        int rem = t - which * 392;
        int row = rem >> 3, c4 = (rem & 7) * 4;
        float4 val = *reinterpret_cast<const float4*>(
            base + (size_t)which * ROWSTRIDE + row * 32 + c4);
        float* dst = (which == 0) ? sq : (which == 1) ? sk : sv;
        *reinterpret_cast<float4*>(&dst[row * 36 + c4]) = val;
    }
    for (int t = tid; t < 169; t += 64) sPos[t] = pos[t];
    __syncthreads();

    const float SCALE = 0.17677669529663687f;   // 1/sqrt(32)
    const float NEG_INF = __int_as_float(0xff800000u);
    const bool mu = (u == 7), mv = (v == 7);

    // S = q @ k^T : 7x7 thread grid, each computes a 7x7 register tile
    if (tid < 49) {
        int qt = tid / 7, kt = tid - qt * 7;
        float s[7][7];
#pragma unroll
        for (int i = 0; i < 7; i++)
#pragma unroll
            for (int j = 0; j < 7; j++) s[i][j] = 0.f;
        for (int e = 0; e < 32; e++) {
            float qv[7], kv[7];
#pragma unroll
            for (int i = 0; i < 7; i++) {
                qv[i] = sq[(qt * 7 + i) * 36 + e];
                kv[i] = sk[(kt * 7 + i) * 36 + e];
            }
#pragma unroll
            for (int i = 0; i < 7; i++)
#pragma unroll
                for (int j = 0; j < 7; j++) s[i][j] += qv[i] * kv[j];
        }
#pragma unroll
        for (int i = 0; i < 7; i++) {
#pragma unroll
            for (int j = 0; j < 7; j++) {
                // q = qt*7+i -> (qx,qy)=(qt,i);  k = kt*7+j -> (kx,ky)=(kt,j)
                float val = s[i][j] * SCALE + sPos[(kt - qt + 6) * 13 + (j - i + 6)];
                if (mu && ((qt >= 4) != (kt >= 4))) val = NEG_INF;
                if (mv && ((i >= 4) != (j >= 4)))   val = NEG_INF;
                sS[(qt * 7 + i) * 50 + (kt * 7 + j)] = val;
            }
        }
    }
    __syncthreads();

    // softmax: one thread per query row
    if (tid < 49) {
        float m = -1e30f;
        for (int k = 0; k < WSZ; k++) m = fmaxf(m, sS[tid * 50 + k]);
        float sum = 0.f;
        for (int k = 0; k < WSZ; k++) {
            float e = __expf(sS[tid * 50 + k] - m);
            sS[tid * 50 + k] = e;
            sum += e;
        }
        float inv = 1.f / sum;
        for (int k = 0; k < WSZ; k++) sS[tid * 50 + k] *= inv;
    }
    __syncthreads();

    // O = P @ v : thread (qt, et) computes 7 queries x 4 channels
    if (tid < 56) {
        int qt = tid >> 3, et = tid & 7;
        float acc[7][4];
#pragma unroll
        for (int i = 0; i < 7; i++)
#pragma unroll
            for (int cc = 0; cc < 4; cc++) acc[i][cc] = 0.f;
        for (int k = 0; k < WSZ; k++) {
            float vv[4];
#pragma unroll
            for (int cc = 0; cc < 4; cc++) vv[cc] = sv[k * 36 + et * 4 + cc];
#pragma unroll
            for (int i = 0; i < 7; i++) {
                float p = sS[(qt * 7 + i) * 50 + k];
#pragma unroll
                for (int cc = 0; cc < 4; cc++) acc[i][cc] += p * vv[cc];
            }
        }
        // q = qt*7+i -> (wx,wy)=(qt,i); write with roll(+3)
        int yo = u * 7 + qt + 3; if (yo >= 56) yo -= 56;
#pragma unroll
        for (int i = 0; i < 7; i++) {
            int xo = v * 7 + i + 3; if (xo >= 56) xo -= 56;
            size_t o = ((size_t)((b * 56 + yo) * 56 + xo)) * 256 + head;
#pragma unroll
            for (int cc = 0; cc < 4; cc++)
                out[o + (size_t)(et * 4 + cc) * 8] = acc[i][cc];
        }
    }
}

// ---------------------------------------------------------------------------
extern "C" void kernel_launch(void* const* d_in, const int* in_sizes, int n_in,
                              void* d_out, int out_size) {
    const float* x   = (const float*)d_in[0];
    const float* w1  = (const float*)d_in[1];
    const float* b1  = (const float*)d_in[2];
    const float* pos = (const float*)d_in[3];
    float* out = (float*)d_out;

    permute_w1_kernel<<<768, 256>>>(w1, b1);
    qkv_gemm_kernel<<<dim3(784, 6), 256>>>(x);
    attn_kernel<<<16384, 64>>>(pos, out);
}

// round 2
// speedup vs baseline: 1.1737x; 1.1737x over previous
#include <cuda_runtime.h>
#include <cstdint>

// ---------------------------------------------------------------------------
// ShiftedWindowMSA  (B=32, 56x56, EMB=256, 8 heads, 7x7 windows)
// Stage 1: permute w1 columns (head/which/e split -> contiguous groups)
// Stage 2: QKV GEMM (tf32 mma), epilogue scatters via roll(-4)+window split
// Stage 3: per-window attention, NOW on tensor cores (tf32 mma), fused
//          bias + shift masks + softmax + inverse roll(+3) output.
// ---------------------------------------------------------------------------

#define NB    32
#define WSZ   49
#define ROWSTRIDE 100352        // 64 windows * 49 * 32 per (b,g)

__device__ float g_scr[(size_t)NB * 24 * ROWSTRIDE];
__device__ float g_w1p[256 * 768];
__device__ float g_b1p[768];

__device__ __forceinline__ float to_tf32(float x) {
    uint32_t u;
    asm("cvt.rna.tf32.f32 %0, %1;" : "=r"(u) : "f"(x));
    return __uint_as_float(u);
}

__device__ __forceinline__ void mma_tf32(float c[4], uint32_t a0, uint32_t a1,
                                         uint32_t a2, uint32_t a3,
                                         uint32_t b0, uint32_t b1) {
    asm volatile(
        "mma.sync.aligned.m16n8k8.row.col.f32.tf32.tf32.f32 "
        "{%0,%1,%2,%3}, {%4,%5,%6,%7}, {%8,%9}, {%0,%1,%2,%3};"
        : "+f"(c[0]), "+f"(c[1]), "+f"(c[2]), "+f"(c[3])
        : "r"(a0), "r"(a1), "r"(a2), "r"(a3), "r"(b0), "r"(b1));
}

// ---------------------------------------------------------------------------
__global__ void permute_w1_kernel(const float* __restrict__ w1,
                                  const float* __restrict__ b1) {
    int idx = blockIdx.x * blockDim.x + threadIdx.x;
    if (idx < 256 * 768) {
        int k = idx / 768, jn = idx - k * 768;
        int g = jn >> 5, e = jn & 31;
        g_w1p[idx] = w1[k * 768 + e * 24 + g];
    }
    if (idx < 768) {
        int g = idx >> 5, e = idx & 31;
        g_b1p[idx] = b1[e * 24 + g];
    }
}

// ---------------------------------------------------------------------------
// Stage 2: QKV GEMM  C[100352,768] = x @ w1p + b1p
//   grid = (6 n-tiles, 784 m-tiles) so consecutive blocks reuse the A tile
//   (x stays hot in L2: ~110MB A traffic instead of 620MB).
// ---------------------------------------------------------------------------
#define BM 128
#define BN 128
#define BK 32
#define ASTR 36
#define BSTR 136

__global__ __launch_bounds__(256) void qkv_gemm_kernel(const float* __restrict__ x) {
    __shared__ float As[BM * ASTR];
    __shared__ float Bs[BK * BSTR];

    const int tid  = threadIdx.x;
    const int warp = tid >> 5, lane = tid & 31;
    const int tg = lane >> 2, t4 = lane & 3;
    const int wm0 = (warp >> 2) * 64;
    const int wn0 = (warp & 3) * 32;
    const int tile_m = blockIdx.y * BM;
    const int tile_n = blockIdx.x * BN;

    float c[4][4][4];
#pragma unroll
    for (int a = 0; a < 4; a++)
#pragma unroll
        for (int b = 0; b < 4; b++)
#pragma unroll
            for (int d = 0; d < 4; d++) c[a][b][d] = 0.f;

    for (int ki = 0; ki < 256; ki += BK) {
#pragma unroll
        for (int j = 0; j < 4; j++) {
            int f = tid + j * 256;
            int row = f >> 3, c4 = (f & 7) * 4;
            float4 va = *reinterpret_cast<const float4*>(
                x + (size_t)(tile_m + row) * 256 + ki + c4);
            float4 t;
            t.x = to_tf32(va.x); t.y = to_tf32(va.y);
            t.z = to_tf32(va.z); t.w = to_tf32(va.w);
            *reinterpret_cast<float4*>(&As[row * ASTR + c4]) = t;
        }
#pragma unroll
        for (int j = 0; j < 4; j++) {
            int f = tid + j * 256;
            int kr = f >> 5, c4 = (f & 31) * 4;
            float4 vb = *reinterpret_cast<const float4*>(
                &g_w1p[(size_t)(ki + kr) * 768 + tile_n + c4]);
            float4 t;
            t.x = to_tf32(vb.x); t.y = to_tf32(vb.y);
            t.z = to_tf32(vb.z); t.w = to_tf32(vb.w);
            *reinterpret_cast<float4*>(&Bs[kr * BSTR + c4]) = t;
        }
        __syncthreads();

#pragma unroll
        for (int kk = 0; kk < 32; kk += 8) {
            uint32_t a[4][4], bf[4][2];
#pragma unroll
            for (int mt = 0; mt < 4; mt++) {
                int r = wm0 + mt * 16 + tg;
                a[mt][0] = __float_as_uint(As[r * ASTR + kk + t4]);
                a[mt][1] = __float_as_uint(As[(r + 8) * ASTR + kk + t4]);
                a[mt][2] = __float_as_uint(As[r * ASTR + kk + t4 + 4]);
                a[mt][3] = __float_as_uint(As[(r + 8) * ASTR + kk + t4 + 4]);
            }
#pragma unroll
            for (int nt = 0; nt < 4; nt++) {
                int cn = wn0 + nt * 8 + tg;
                bf[nt][0] = __float_as_uint(Bs[(kk + t4) * BSTR + cn]);
                bf[nt][1] = __float_as_uint(Bs[(kk + t4 + 4) * BSTR + cn]);
            }
#pragma unroll
            for (int mt = 0; mt < 4; mt++)
#pragma unroll
                for (int nt = 0; nt < 4; nt++)
                    mma_tf32(c[mt][nt], a[mt][0], a[mt][1], a[mt][2], a[mt][3],
                             bf[nt][0], bf[nt][1]);
        }
        __syncthreads();
    }

    size_t rowbase[8];
#pragma unroll
    for (int mt = 0; mt < 4; mt++) {
#pragma unroll
        for (int h = 0; h < 2; h++) {
            int n = tile_m + wm0 + mt * 16 + tg + h * 8;
            int b = n / 3136;
            int r = n - b * 3136;
            int y = r / 56, xx = r - y * 56;
            int yr = (y + 52) % 56;
            int xr = (xx + 52) % 56;
            int u = yr / 7, wxr = yr - u * 7;
            int v = xr / 7, wyr = xr - v * 7;
            rowbase[mt * 2 + h] = (size_t)(b * 24) * ROWSTRIDE
                                + (size_t)(u * 8 + v) * (WSZ * 32)
                                + (size_t)(wxr * 7 + wyr) * 32;
        }
    }
#pragma unroll
    for (int nt = 0; nt < 4; nt++) {
        int jn0 = tile_n + wn0 + nt * 8 + t4 * 2;
        float bias0 = g_b1p[jn0];
        float bias1 = g_b1p[jn0 + 1];
        int g0 = jn0 >> 5, e0 = jn0 & 31;
        size_t coff = (size_t)g0 * ROWSTRIDE + e0;
#pragma unroll
        for (int mt = 0; mt < 4; mt++) {
            g_scr[rowbase[mt * 2 + 0] + coff]     = c[mt][nt][0] + bias0;
            g_scr[rowbase[mt * 2 + 0] + coff + 1] = c[mt][nt][1] + bias1;
            g_scr[rowbase[mt * 2 + 1] + coff]     = c[mt][nt][2] + bias0;
            g_scr[rowbase[mt * 2 + 1] + coff + 1] = c[mt][nt][3] + bias1;
        }
    }
}

// ---------------------------------------------------------------------------
// Stage 3: tensor-core attention. 128 threads (4 warps) per (b, head, window).
//   Warp w owns S rows 16w..16w+15 (m padded 49->64, n padded 49->56,
//   P pad columns zeroed so P@V pad contributions are exact zeros).
// ---------------------------------------------------------------------------
__global__ __launch_bounds__(128) void attn_kernel(const float* __restrict__ pos,
                                                   float* __restrict__ out) {
    __shared__ float sq[64 * 36];
    __shared__ float sk[56 * 36];
    __shared__ float sv[56 * 36];
    __shared__ float sS[64 * 60];
    __shared__ float sPos[169];

    const int tid = threadIdx.x;
    const int warp = tid >> 5, lane = tid & 31;
    const int tg = lane >> 2, t4 = lane & 3;
    const int bid = blockIdx.x;
    const int b    = bid >> 9;
    const int head = (bid >> 6) & 7;
    const int win  = bid & 63;
    const int u = win >> 3, v = win & 7;
    const bool mu = (u == 7), mv = (v == 7);

    const float* base = g_scr + (size_t)(b * 24 + head * 3) * ROWSTRIDE
                              + (size_t)win * (WSZ * 32);

    // load q,k,v (tf32-rounded at load): 3 * 49 rows * 8 float4
    for (int t = tid; t < 1176; t += 128) {
        int which = t / 392;
        int rem = t - which * 392;
        int row = rem >> 3, c4 = (rem & 7) * 4;
        float4 val = *reinterpret_cast<const float4*>(
            base + (size_t)which * ROWSTRIDE + row * 32 + c4);
        float4 tt;
        tt.x = to_tf32(val.x); tt.y = to_tf32(val.y);
        tt.z = to_tf32(val.z); tt.w = to_tf32(val.w);
        float* dst = (which == 0) ? sq : (which == 1) ? sk : sv;
        *reinterpret_cast<float4*>(&dst[row * 36 + c4]) = tt;
    }
    // zero V pad rows 49..55 (avoid 0*inf=NaN in P@V)
    for (int t = tid; t < 7 * 36; t += 128) sv[49 * 36 + t] = 0.f;
    for (int t = tid; t < 169; t += 128) sPos[t] = pos[t];
    __syncthreads();

    const int row0 = warp * 16 + tg;
    const int row1 = row0 + 8;

    // ---- S = q @ k^T (tf32 mma), 16x56 per warp ----
    float cS[7][4];
#pragma unroll
    for (int nt = 0; nt < 7; nt++)
#pragma unroll
        for (int d = 0; d < 4; d++) cS[nt][d] = 0.f;

#pragma unroll
    for (int kk = 0; kk < 32; kk += 8) {
        uint32_t a0 = __float_as_uint(sq[row0 * 36 + kk + t4]);
        uint32_t a1 = __float_as_uint(sq[row1 * 36 + kk + t4]);
        uint32_t a2 = __float_as_uint(sq[row0 * 36 + kk + t4 + 4]);
        uint32_t a3 = __float_as_uint(sq[row1 * 36 + kk + t4 + 4]);
#pragma unroll
        for (int nt = 0; nt < 7; nt++) {
            int n = nt * 8 + tg;
            uint32_t b0 = __float_as_uint(sk[n * 36 + kk + t4]);
            uint32_t b1 = __float_as_uint(sk[n * 36 + kk + t4 + 4]);
            mma_tf32(cS[nt], a0, a1, a2, a3, b0, b1);
        }
    }

    // ---- scale + bias + masks, store S rows < 49 ----
    const float SCALE = 0.17677669529663687f;   // 1/sqrt(32)
    const float NEG_INF = __int_as_float(0xff800000u);
#pragma unroll
    for (int r = 0; r < 2; r++) {
        int row = r ? row1 : row0;
        if (row < 49) {
            int qt = (row * 9363) >> 16;
            int ii = row - qt * 7;
            bool pq = (qt >= 4), pi = (ii >= 4);
#pragma unroll
            for (int nt = 0; nt < 7; nt++) {
                int col = nt * 8 + 2 * t4;
#pragma unroll
                for (int d = 0; d < 2; d++) {
                    int cc = col + d;
                    int kt = (cc * 9363) >> 16;
                    int jj = cc - kt * 7;
                    float val = cS[nt][r * 2 + d] * SCALE
                              + sPos[(kt - qt + 6) * 13 + (jj - ii + 6)];
                    if (mu && (pq != (kt >= 4))) val = NEG_INF;
                    if (mv && (pi != (jj >= 4))) val = NEG_INF;
                    sS[row * 60 + cc] = val;
                }
            }
        }
    }
    __syncthreads();

    // ---- softmax per row (threads 0..48), pad cols 49..55 -> 0 ----
    if (tid < 49) {
        float* rowp = &sS[tid * 60];
        float m = -1e30f;
#pragma unroll 7
        for (int k = 0; k < WSZ; k++) m = fmaxf(m, rowp[k]);
        float sum = 0.f;
#pragma unroll 7
        for (int k = 0; k < WSZ; k++) {
            float e = __expf(rowp[k] - m);
            rowp[k] = e;
            sum += e;
        }
        float inv = 1.f / sum;
#pragma unroll 7
        for (int k = 0; k < WSZ; k++) rowp[k] = to_tf32(rowp[k] * inv);
#pragma unroll
        for (int k = WSZ; k < 56; k++) rowp[k] = 0.f;
    }
    __syncthreads();

    // ---- O = P @ v (tf32 mma), 16x32 per warp ----
    float cO[4][4];
#pragma unroll
    for (int nt = 0; nt < 4; nt++)
#pragma unroll
        for (int d = 0; d < 4; d++) cO[nt][d] = 0.f;

#pragma unroll
    for (int kk = 0; kk < 56; kk += 8) {
        uint32_t a0 = __float_as_uint(sS[row0 * 60 + kk + t4]);
        uint32_t a1 = __float_as_uint(sS[row1 * 60 + kk + t4]);
        uint32_t a2 = __float_as_uint(sS[row0 * 60 + kk + t4 + 4]);
        uint32_t a3 = __float_as_uint(sS[row1 * 60 + kk + t4 + 4]);
#pragma unroll
        for (int nt = 0; nt < 4; nt++) {
            int n = nt * 8 + tg;
            uint32_t b0 = __float_as_uint(sv[(kk + t4) * 36 + n]);
            uint32_t b1 = __float_as_uint(sv[(kk + t4 + 4) * 36 + n]);
            mma_tf32(cO[nt], a0, a1, a2, a3, b0, b1);
        }
    }

    // ---- store output with inverse roll(+3); channel = e*8 + head ----
#pragma unroll
    for (int r = 0; r < 2; r++) {
        int row = r ? row1 : row0;
        if (row < 49) {
            int qt = (row * 9363) >> 16;
            int ii = row - qt * 7;
            int yo = u * 7 + qt + 3; if (yo >= 56) yo -= 56;
            int xo = v * 7 + ii + 3; if (xo >= 56) xo -= 56;
            float* op = out + ((size_t)((b * 56 + yo) * 56 + xo)) * 256 + head;
#pragma unroll
            for (int nt = 0; nt < 4; nt++) {
                int e0 = nt * 8 + 2 * t4;
                op[(size_t)e0 * 8]       = cO[nt][r * 2 + 0];
                op[(size_t)(e0 + 1) * 8] = cO[nt][r * 2 + 1];
            }
        }
    }
}

// ---------------------------------------------------------------------------
extern "C" void kernel_launch(void* const* d_in, const int* in_sizes, int n_in,
                              void* d_out, int out_size) {
    const float* x   = (const float*)d_in[0];
    const float* w1  = (const float*)d_in[1];
    const float* b1  = (const float*)d_in[2];
    const float* pos = (const float*)d_in[3];
    float* out = (float*)d_out;

    permute_w1_kernel<<<768, 256>>>(w1, b1);
    qkv_gemm_kernel<<<dim3(6, 784), 256>>>(x);
    attn_kernel<<<16384, 128>>>(pos, out);
}